// round 9
// baseline (speedup 1.0000x reference)
#include <cuda_runtime.h>

// Problem constants (fixed by the reference: B=8, S=2048, D=1024)
#define BB 8
#define SS 2048
#define DD 1024
#define CHUNKS 128
#define ROWS_PER_CHUNK (SS / CHUNKS)   // 16
#define NRED 8                          // reducer CTAs per batch (one per 128-col group)

// Scratch (written, never accumulated -> no zero-init needed).
__device__ float g_partial[BB * CHUNKS * DD];   // 4 MB
__device__ float g_xsum[BB * DD];               // 32 KB
__device__ int   g_cnt[BB];                     // zero at load; self-resetting per launch

// ---------------------------------------------------------------------------
// Kernel A (fused): per-(batch, chunk) column sum + last-8-CTAs reduce.
// grid = (128, 8) = 1024 CTAs, block = 256. All CTAs are co-resident
// (<=36 regs, 256 thr, 4KB smem -> 7 CTAs/SM * 148 = 1036 >= 1024), so the
// short spin below cannot deadlock.
//
// Phase 1: CTA (c, b) sums its 16 rows into g_partial[b][c][:].
// Phase 2: the last 8 arriving CTAs of batch b (arrival ranks CHUNKS-8 ..
//          CHUNKS-1 from the atomic counter) each take column-group
//          g = rank-(CHUNKS-8), spin until all 128 partials of batch b are
//          published, then fold chunks in a FIXED order into g_xsum.
//          Disjoint outputs + fixed fold order => bitwise-deterministic.
// Counter protocol: 128 pre-increments, then 8 post-increments; the reducer
// that sees old == CHUNKS+7 resets the counter for the next graph replay.
// ---------------------------------------------------------------------------
__global__ __launch_bounds__(256) void colsum_fused_kernel(const float* __restrict__ x) {
    __shared__ float4 red[8][32];
    __shared__ int s_rank;

    const int c = blockIdx.x;
    const int b = blockIdx.y;
    const int t = threadIdx.x;

    // ---- Phase 1: chunk column sum -------------------------------------
    {
        const float4* __restrict__ xp =
            reinterpret_cast<const float4*>(x + ((size_t)b * SS + (size_t)c * ROWS_PER_CHUNK) * DD) + t;

        float4 a0 = make_float4(0.f, 0.f, 0.f, 0.f);
        float4 a1 = make_float4(0.f, 0.f, 0.f, 0.f);
        float4 a2 = make_float4(0.f, 0.f, 0.f, 0.f);
        float4 a3 = make_float4(0.f, 0.f, 0.f, 0.f);

        #pragma unroll
        for (int s = 0; s < ROWS_PER_CHUNK; s += 4) {
            float4 v0 = xp[(size_t)(s + 0) * (DD / 4)];
            float4 v1 = xp[(size_t)(s + 1) * (DD / 4)];
            float4 v2 = xp[(size_t)(s + 2) * (DD / 4)];
            float4 v3 = xp[(size_t)(s + 3) * (DD / 4)];
            a0.x += v0.x; a0.y += v0.y; a0.z += v0.z; a0.w += v0.w;
            a1.x += v1.x; a1.y += v1.y; a1.z += v1.z; a1.w += v1.w;
            a2.x += v2.x; a2.y += v2.y; a2.z += v2.z; a2.w += v2.w;
            a3.x += v3.x; a3.y += v3.y; a3.z += v3.z; a3.w += v3.w;
        }

        float4 acc;
        acc.x = (a0.x + a1.x) + (a2.x + a3.x);
        acc.y = (a0.y + a1.y) + (a2.y + a3.y);
        acc.z = (a0.z + a1.z) + (a2.z + a3.z);
        acc.w = (a0.w + a1.w) + (a2.w + a3.w);

        reinterpret_cast<float4*>(g_partial + ((size_t)b * CHUNKS + c) * DD)[t] = acc;
    }

    // ---- Publish + arrival rank ----------------------------------------
    __threadfence();   // make this CTA's partial visible before the count
    if (t == 0) s_rank = atomicAdd(&g_cnt[b], 1);
    __syncthreads();
    const int rank = s_rank;
    if (rank < CHUNKS - NRED) return;          // not a reducer

    // ---- Phase 2: reducer for column-group g ---------------------------
    const int g = rank - (CHUNKS - NRED);      // 0..7, unique per batch

    if (t == 0) {
        // Wait until all 128 partials of batch b are published.
        while (*((volatile int*)&g_cnt[b]) < CHUNKS) { }
    }
    __syncthreads();

    {
        const int tx = t & 31;                 // float4 col within group
        const int ty = t >> 5;                 // chunk sub-group
        const int c4 = g * 32 + tx;            // float4 column (0..255)
        const float4* __restrict__ pp =
            reinterpret_cast<const float4*>(g_partial + (size_t)b * CHUNKS * DD) + c4;

        float4 a = make_float4(0.f, 0.f, 0.f, 0.f);
        #pragma unroll
        for (int q = 0; q < 16; q += 8) {
            float4 v0 = pp[(size_t)(ty * 16 + q + 0) * (DD / 4)];
            float4 v1 = pp[(size_t)(ty * 16 + q + 1) * (DD / 4)];
            float4 v2 = pp[(size_t)(ty * 16 + q + 2) * (DD / 4)];
            float4 v3 = pp[(size_t)(ty * 16 + q + 3) * (DD / 4)];
            float4 v4 = pp[(size_t)(ty * 16 + q + 4) * (DD / 4)];
            float4 v5 = pp[(size_t)(ty * 16 + q + 5) * (DD / 4)];
            float4 v6 = pp[(size_t)(ty * 16 + q + 6) * (DD / 4)];
            float4 v7 = pp[(size_t)(ty * 16 + q + 7) * (DD / 4)];
            a.x += ((v0.x + v1.x) + (v2.x + v3.x)) + ((v4.x + v5.x) + (v6.x + v7.x));
            a.y += ((v0.y + v1.y) + (v2.y + v3.y)) + ((v4.y + v5.y) + (v6.y + v7.y));
            a.z += ((v0.z + v1.z) + (v2.z + v3.z)) + ((v4.z + v5.z) + (v6.z + v7.z));
            a.w += ((v0.w + v1.w) + (v2.w + v3.w)) + ((v4.w + v5.w) + (v6.w + v7.w));
        }

        red[ty][tx] = a;
        __syncthreads();

        if (ty == 0) {
            float4 r0 = red[0][tx], r1 = red[1][tx], r2 = red[2][tx], r3 = red[3][tx];
            float4 r4 = red[4][tx], r5 = red[5][tx], r6 = red[6][tx], r7 = red[7][tx];
            float4 s;
            s.x = ((r0.x + r1.x) + (r2.x + r3.x)) + ((r4.x + r5.x) + (r6.x + r7.x));
            s.y = ((r0.y + r1.y) + (r2.y + r3.y)) + ((r4.y + r5.y) + (r6.y + r7.y));
            s.z = ((r0.z + r1.z) + (r2.z + r3.z)) + ((r4.z + r5.z) + (r6.z + r7.z));
            s.w = ((r0.w + r1.w) + (r2.w + r3.w)) + ((r4.w + r5.w) + (r6.w + r7.w));
            reinterpret_cast<float4*>(g_xsum + (size_t)b * DD)[c4] = s;
        }
    }

    // ---- Counter self-reset for graph replay ---------------------------
    __syncthreads();
    if (t == 0) {
        int o2 = atomicAdd(&g_cnt[b], 1);      // olds CHUNKS .. CHUNKS+7
        if (o2 == CHUNKS + NRED - 1)
            atomicExch(&g_cnt[b], 0);          // last reducer resets
    }
}

// ---------------------------------------------------------------------------
// Kernel B: out[b, e] = dot(xsum[b,:], Wv[e,:]) + S * bv[e]
// grid = 128 CTAs, block = 256 (8 warps). Smem-staged; each warp owns one
// Wv row and dots it against all 8 batches. (Measured-good; unchanged.)
// ---------------------------------------------------------------------------
__global__ __launch_bounds__(256) void gemv_kernel(const float* __restrict__ Wv,
                                                   const float* __restrict__ bv,
                                                   float* __restrict__ out) {
    __shared__ float xs[BB * DD];   // 32 KB

    const int t = threadIdx.x;

    {
        const float4* __restrict__ src = reinterpret_cast<const float4*>(g_xsum);
        float4*       __restrict__ dst = reinterpret_cast<float4*>(xs);
        #pragma unroll
        for (int i = 0; i < (BB * DD / 4) / 256; ++i)   // 8 iterations
            dst[t + 256 * i] = src[t + 256 * i];
    }
    __syncthreads();

    const int warp = t >> 5;
    const int lane = t & 31;
    const int e = blockIdx.x * 8 + warp;

    const float4* __restrict__ wrow = reinterpret_cast<const float4*>(Wv + (size_t)e * DD);

    float s0 = 0.f, s1 = 0.f, s2 = 0.f, s3 = 0.f;
    float s4 = 0.f, s5 = 0.f, s6 = 0.f, s7 = 0.f;

    #pragma unroll
    for (int i = 0; i < 8; ++i) {
        const int c4 = lane + 32 * i;
        float4 w = wrow[c4];
        #define ACC(bi, s) { \
            float4 xv = reinterpret_cast<const float4*>(xs + (bi) * DD)[c4]; \
            s += w.x * xv.x + w.y * xv.y + w.z * xv.z + w.w * xv.w; }
        ACC(0, s0) ACC(1, s1) ACC(2, s2) ACC(3, s3)
        ACC(4, s4) ACC(5, s5) ACC(6, s6) ACC(7, s7)
        #undef ACC
    }

    #pragma unroll
    for (int off = 16; off; off >>= 1) {
        s0 += __shfl_xor_sync(0xffffffffu, s0, off);
        s1 += __shfl_xor_sync(0xffffffffu, s1, off);
        s2 += __shfl_xor_sync(0xffffffffu, s2, off);
        s3 += __shfl_xor_sync(0xffffffffu, s3, off);
        s4 += __shfl_xor_sync(0xffffffffu, s4, off);
        s5 += __shfl_xor_sync(0xffffffffu, s5, off);
        s6 += __shfl_xor_sync(0xffffffffu, s6, off);
        s7 += __shfl_xor_sync(0xffffffffu, s7, off);
    }

    if (lane == 0) {
        const float bias = (float)SS * bv[e];
        out[0 * DD + e] = s0 + bias;
        out[1 * DD + e] = s1 + bias;
        out[2 * DD + e] = s2 + bias;
        out[3 * DD + e] = s3 + bias;
        out[4 * DD + e] = s4 + bias;
        out[5 * DD + e] = s5 + bias;
        out[6 * DD + e] = s6 + bias;
        out[7 * DD + e] = s7 + bias;
    }
}

// ---------------------------------------------------------------------------
// kernel_launch — graph-capturable, allocation-free, deterministic.
// Input order (metadata): 0=x, 1=Wq, 2=bq, 3=Wk, 4=bk, 5=Wv, 6=bv
// ---------------------------------------------------------------------------
extern "C" void kernel_launch(void* const* d_in, const int* in_sizes, int n_in,
                              void* d_out, int out_size) {
    (void)in_sizes; (void)n_in; (void)out_size;
    const float* x  = (const float*)d_in[0];
    const float* Wv = (const float*)d_in[5];
    const float* bv = (const float*)d_in[6];
    float* out = (float*)d_out;

    colsum_fused_kernel<<<dim3(CHUNKS, BB), 256>>>(x);
    gemv_kernel<<<DD / 8, 256>>>(Wv, bv, out);
}

// round 10
// speedup vs baseline: 1.2765x; 1.2765x over previous
#include <cuda_runtime.h>

// Problem constants (fixed by the reference: B=8, S=2048, D=1024)
#define BB 8
#define SS 2048
#define DD 1024
#define CHUNKS 64
#define ROWS_PER_CHUNK (SS / CHUNKS)   // 32
#define GEMV_CTAS 128                   // <= #SMs -> all co-resident (spin-safe)

// Scratch (written, never accumulated -> no zero-init needed).
__device__ float g_partial[BB * CHUNKS * DD];   // 2 MB
__device__ float g_xsum[BB * DD];               // 32 KB
__device__ int   g_cnt;                         // reduce-publish counter (self-resetting)
__device__ int   g_done;                        // exit counter for reset handshake

// ---------------------------------------------------------------------------
// Kernel A: per-(batch, chunk) column sum of x over S.  [R7 measured-good]
// grid = (64, 8) = 512 CTAs, block = 256; thread t owns float4 column t.
// ---------------------------------------------------------------------------
__global__ __launch_bounds__(256) void colsum_kernel(const float* __restrict__ x) {
    const int c = blockIdx.x;
    const int b = blockIdx.y;
    const int t = threadIdx.x;

    const float4* __restrict__ xp =
        reinterpret_cast<const float4*>(x + ((size_t)b * SS + (size_t)c * ROWS_PER_CHUNK) * DD) + t;

    float4 a0 = make_float4(0.f, 0.f, 0.f, 0.f);
    float4 a1 = make_float4(0.f, 0.f, 0.f, 0.f);
    float4 a2 = make_float4(0.f, 0.f, 0.f, 0.f);
    float4 a3 = make_float4(0.f, 0.f, 0.f, 0.f);

    #pragma unroll
    for (int s = 0; s < ROWS_PER_CHUNK; s += 8) {
        float4 v0 = xp[(size_t)(s + 0) * (DD / 4)];
        float4 v1 = xp[(size_t)(s + 1) * (DD / 4)];
        float4 v2 = xp[(size_t)(s + 2) * (DD / 4)];
        float4 v3 = xp[(size_t)(s + 3) * (DD / 4)];
        float4 v4 = xp[(size_t)(s + 4) * (DD / 4)];
        float4 v5 = xp[(size_t)(s + 5) * (DD / 4)];
        float4 v6 = xp[(size_t)(s + 6) * (DD / 4)];
        float4 v7 = xp[(size_t)(s + 7) * (DD / 4)];
        a0.x += v0.x; a0.y += v0.y; a0.z += v0.z; a0.w += v0.w;
        a1.x += v1.x; a1.y += v1.y; a1.z += v1.z; a1.w += v1.w;
        a2.x += v2.x; a2.y += v2.y; a2.z += v2.z; a2.w += v2.w;
        a3.x += v3.x; a3.y += v3.y; a3.z += v3.z; a3.w += v3.w;
        a0.x += v4.x; a0.y += v4.y; a0.z += v4.z; a0.w += v4.w;
        a1.x += v5.x; a1.y += v5.y; a1.z += v5.z; a1.w += v5.w;
        a2.x += v6.x; a2.y += v6.y; a2.z += v6.z; a2.w += v6.w;
        a3.x += v7.x; a3.y += v7.y; a3.z += v7.z; a3.w += v7.w;
    }

    float4 acc;
    acc.x = (a0.x + a1.x) + (a2.x + a3.x);
    acc.y = (a0.y + a1.y) + (a2.y + a3.y);
    acc.z = (a0.z + a1.z) + (a2.z + a3.z);
    acc.w = (a0.w + a1.w) + (a2.w + a3.w);

    reinterpret_cast<float4*>(g_partial + ((size_t)b * CHUNKS + c) * DD)[t] = acc;
}

// ---------------------------------------------------------------------------
// Kernel B (fused reduce + gemv): grid = 128 CTAs, block = 256.
// Phase 1: CTA k reduces xsum float4 slice [k*16, k*16+16) over all 64 chunks
//          (16 chunk-groups x 4 chunks, fixed fold order -> deterministic),
//          writes to g_xsum, fences, counts.
// Sync:    all 128 CTAs are co-resident (grid <= SM count) -> spin on g_cnt.
// Phase 2: the measured-good gemv — stage all 8 xsum vectors to smem, warp
//          owns Wv row e, dots against all 8 batches.
// Reset:   g_done second round; last CTA zeroes both counters (replay-safe).
// ---------------------------------------------------------------------------
__global__ __launch_bounds__(256) void gemv_fused_kernel(const float* __restrict__ Wv,
                                                         const float* __restrict__ bv,
                                                         float* __restrict__ out) {
    __shared__ float  xs[BB * DD];      // 32 KB
    __shared__ float4 red[16][16];      // 4 KB

    const int t   = threadIdx.x;
    const int cta = blockIdx.x;         // 0..127

    // ---- Phase 1: reduce this CTA's 16 float4 columns of xsum ----------
    {
        const int tx = t & 15;                  // col within slice
        const int tg = t >> 4;                  // chunk group 0..15
        const int gc4  = cta * 16 + tx;         // global float4 col in [0,2048)
        const int b    = gc4 >> 8;              // batch (256 float4 per batch)
        const int col4 = gc4 & 255;

        const float4* __restrict__ pp =
            reinterpret_cast<const float4*>(g_partial) + (size_t)b * CHUNKS * (DD / 4) + col4;

        float4 v0 = pp[(size_t)(tg * 4 + 0) * (DD / 4)];
        float4 v1 = pp[(size_t)(tg * 4 + 1) * (DD / 4)];
        float4 v2 = pp[(size_t)(tg * 4 + 2) * (DD / 4)];
        float4 v3 = pp[(size_t)(tg * 4 + 3) * (DD / 4)];
        float4 a;
        a.x = (v0.x + v1.x) + (v2.x + v3.x);
        a.y = (v0.y + v1.y) + (v2.y + v3.y);
        a.z = (v0.z + v1.z) + (v2.z + v3.z);
        a.w = (v0.w + v1.w) + (v2.w + v3.w);
        red[tg][tx] = a;
        __syncthreads();

        if (tg == 0) {
            float4 s = make_float4(0.f, 0.f, 0.f, 0.f);
            #pragma unroll
            for (int g = 0; g < 16; ++g) {      // fixed order -> deterministic
                float4 r = red[g][tx];
                s.x += r.x; s.y += r.y; s.z += r.z; s.w += r.w;
            }
            reinterpret_cast<float4*>(g_xsum)[gc4] = s;
        }
    }

    // Publish: writes above must be globally visible before the count.
    __syncthreads();
    __threadfence();
    if (t == 0) atomicAdd(&g_cnt, 1);

    // ---- Grid-wide spin sync (all CTAs resident -> cannot deadlock) ----
    if (t == 0) {
        while (*((volatile int*)&g_cnt) < GEMV_CTAS) { }
    }
    __syncthreads();

    // ---- Phase 2: gemv (unchanged measured-good path) ------------------
    {
        const float4* __restrict__ src = reinterpret_cast<const float4*>(g_xsum);
        float4*       __restrict__ dst = reinterpret_cast<float4*>(xs);
        #pragma unroll
        for (int i = 0; i < (BB * DD / 4) / 256; ++i)   // 8 iterations
            dst[t + 256 * i] = src[t + 256 * i];
    }
    __syncthreads();

    const int warp = t >> 5;
    const int lane = t & 31;
    const int e = cta * 8 + warp;

    const float4* __restrict__ wrow = reinterpret_cast<const float4*>(Wv + (size_t)e * DD);

    float s0 = 0.f, s1 = 0.f, s2 = 0.f, s3 = 0.f;
    float s4 = 0.f, s5 = 0.f, s6 = 0.f, s7 = 0.f;

    #pragma unroll
    for (int i = 0; i < 8; ++i) {
        const int c4 = lane + 32 * i;
        float4 w = wrow[c4];
        #define ACC(bi, s) { \
            float4 xv = reinterpret_cast<const float4*>(xs + (bi) * DD)[c4]; \
            s += w.x * xv.x + w.y * xv.y + w.z * xv.z + w.w * xv.w; }
        ACC(0, s0) ACC(1, s1) ACC(2, s2) ACC(3, s3)
        ACC(4, s4) ACC(5, s5) ACC(6, s6) ACC(7, s7)
        #undef ACC
    }

    #pragma unroll
    for (int off = 16; off; off >>= 1) {
        s0 += __shfl_xor_sync(0xffffffffu, s0, off);
        s1 += __shfl_xor_sync(0xffffffffu, s1, off);
        s2 += __shfl_xor_sync(0xffffffffu, s2, off);
        s3 += __shfl_xor_sync(0xffffffffu, s3, off);
        s4 += __shfl_xor_sync(0xffffffffu, s4, off);
        s5 += __shfl_xor_sync(0xffffffffu, s5, off);
        s6 += __shfl_xor_sync(0xffffffffu, s6, off);
        s7 += __shfl_xor_sync(0xffffffffu, s7, off);
    }

    if (lane == 0) {
        const float bias = (float)SS * bv[e];
        out[0 * DD + e] = s0 + bias;
        out[1 * DD + e] = s1 + bias;
        out[2 * DD + e] = s2 + bias;
        out[3 * DD + e] = s3 + bias;
        out[4 * DD + e] = s4 + bias;
        out[5 * DD + e] = s5 + bias;
        out[6 * DD + e] = s6 + bias;
        out[7 * DD + e] = s7 + bias;
    }

    // ---- Counter reset for graph replay (after all CTAs passed spin) ---
    __syncthreads();
    if (t == 0) {
        int o = atomicAdd(&g_done, 1);
        if (o == GEMV_CTAS - 1) {
            atomicExch(&g_cnt, 0);
            atomicExch(&g_done, 0);
        }
    }
}

// ---------------------------------------------------------------------------
// kernel_launch — graph-capturable, allocation-free, deterministic.
// Input order (metadata): 0=x, 1=Wq, 2=bq, 3=Wk, 4=bk, 5=Wv, 6=bv
// ---------------------------------------------------------------------------
extern "C" void kernel_launch(void* const* d_in, const int* in_sizes, int n_in,
                              void* d_out, int out_size) {
    (void)in_sizes; (void)n_in; (void)out_size;
    const float* x  = (const float*)d_in[0];
    const float* Wv = (const float*)d_in[5];
    const float* bv = (const float*)d_in[6];
    float* out = (float*)d_out;

    colsum_kernel<<<dim3(CHUNKS, BB), 256>>>(x);
    gemv_fused_kernel<<<GEMV_CTAS, 256>>>(Wv, bv, out);
}